// round 4
// baseline (speedup 1.0000x reference)
#include <cuda_runtime.h>
#include <math.h>

#define BSZ 4
#define CC  4
#define NN  2048
#define DD  16
#define KK  32
#define MM  64
#define FULLM 0xffffffffu
typedef unsigned long long ull;
#define INF64 0xFFFFFFFFFFFFFFFFull

// scratch (allocation-free rule: device globals)
__device__ int   g_nbr  [BSZ*CC*NN*KK];
__device__ float g_theta[BSZ*CC*NN*KK];
__device__ float g_gate [BSZ*CC*NN*KK];
__device__ float g_gsum [BSZ*CC*NN];

__device__ __forceinline__ ull warpmin64(ull p) {
    #pragma unroll
    for (int o = 16; o; o >>= 1) {
        ull q = __shfl_xor_sync(FULLM, p, o);
        if (q < p) p = q;
    }
    return p;
}

// ---------------------------------------------------------------------------
// Kernel 1 v4: warp-per-row KNN top-33. Per-lane top-3 register heads +
// REDUX extraction; rare warp-collective refill. 32KB smem, 3 blocks/SM.
// ---------------------------------------------------------------------------
#define ROWS1 16

__global__ __launch_bounds__(512, 3) void knn_kernel(
    const float* __restrict__ pos, const float* __restrict__ node_mask,
    const float* __restrict__ rw1, const float* __restrict__ rw2)
{
    __shared__ float4 spos[NN];            // 32KB
    __shared__ float sSpos;

    const int tid  = threadIdx.x;
    const int warp = tid >> 5;
    const int lane = tid & 31;
    const int slice = blockIdx.y;          // b*C + c
    const int b     = slice >> 2;
    const float* p  = pos + (size_t)slice * NN * 3;

    for (int j = tid; j < NN; j += 512) {
        float x = p[3*j], y = p[3*j+1], z = p[3*j+2];
        float q = fmaf(z, z, fmaf(y, y, x*x));
        spos[j] = make_float4(x, y, z, q);
    }

    // gate MLP collapses: relu(sum_m relu(d*w1)*w2) = relu(d*Spos) for d>=0
    if (tid < 32) {
        float a1 = rw1[tid],    w1v = rw2[tid];
        float a2 = rw1[tid+32], w2v = rw2[tid+32];
        float sp = fmaf(fmaxf(a1, 0.f), w1v, fmaxf(a2, 0.f) * w2v);
        #pragma unroll
        for (int o = 16; o; o >>= 1) sp += __shfl_xor_sync(FULLM, sp, o);
        if (tid == 0) sSpos = sp;
    }
    __syncthreads();

    const int i = blockIdx.x * ROWS1 + warp;
    const float4 pi = spos[i];

    // distance pass: lane owns segment {j : j%32 == lane}; keep sorted top-3
    ull h0 = INF64, h1 = INF64, h2 = INF64;
    #pragma unroll 4
    for (int t = 0; t < 64; t++) {
        const int j = t*32 + lane;
        float4 pj = spos[j];
        float dot = fmaf(pi.z, pj.z, fmaf(pi.y, pj.y, pi.x * pj.x));
        float d   = fmaf(-2.f, dot, pj.w) + pi.w;
        d = fmaxf(d, 0.f);                 // self is exactly 0
        ull pk = ((ull)__float_as_uint(d) << 32) | (unsigned)j;
        if (pk < h2) {
            if (pk < h1) {
                h2 = h1;
                if (pk < h0) { h1 = h0; h0 = pk; }
                else         { h1 = pk; }
            } else h2 = pk;
        }
    }

    // extract 33 smallest ascending (d, j); lane e-1 keeps extraction e
    unsigned nbd = 0; int nbj = 0;
    #pragma unroll 1
    for (int e = 0; e <= 32; e++) {
        unsigned hd   = (unsigned)(h0 >> 32);
        unsigned dmin = __reduce_min_sync(FULLM, hd);
        unsigned cj   = (hd == dmin) ? (unsigned)h0 : 0xffffffffu;
        unsigned jmin = __reduce_min_sync(FULLM, cj);
        if (lane == e - 1) { nbd = dmin; nbj = (int)jmin; }
        if (e == 32) break;
        const int w = (int)(jmin & 31u);
        if (lane == w) { h0 = h1; h1 = h2; h2 = INF64; }
        unsigned hw = __shfl_sync(FULLM, (unsigned)(h0 >> 32), w);
        if (hw == 0xffffffffu) {
            // rare: lane w exhausted -> warp-collective refill of its top-3
            const ull L = ((ull)dmin << 32) | jmin;   // largest extracted so far
            const int j1 = lane*32 + w, j2 = (lane+32)*32 + w;
            float4 a  = spos[j1];
            float4 bb = spos[j2];
            float dota = fmaf(pi.z, a.z,  fmaf(pi.y, a.y,  pi.x * a.x));
            float dotb = fmaf(pi.z, bb.z, fmaf(pi.y, bb.y, pi.x * bb.x));
            float da = fmaxf(fmaf(-2.f, dota, a.w)  + pi.w, 0.f);
            float db = fmaxf(fmaf(-2.f, dotb, bb.w) + pi.w, 0.f);
            ull k1 = ((ull)__float_as_uint(da) << 32) | (unsigned)j1;
            ull k2 = ((ull)__float_as_uint(db) << 32) | (unsigned)j2;
            if (k1 <= L) k1 = INF64;
            if (k2 <= L) k2 = INF64;
            #pragma unroll
            for (int r = 0; r < 3; r++) {
                ull m  = (k1 < k2) ? k1 : k2;
                ull wm = warpmin64(m);
                if (lane == w) {
                    if (r == 0) h0 = wm; else if (r == 1) h1 = wm; else h2 = wm;
                }
                if (k1 == wm) k1 = INF64; else if (k2 == wm) k2 = INF64;
            }
        }
    }

    // lane k holds neighbor k = (nbd, nbj)
    const float mk   = node_mask[b*NN + i];
    const float Spos = sSpos;
    const float dist = __uint_as_float(nbd);
    const int   nb   = nbj;

    const int nb0 = __shfl_sync(FULLM, nbj, 0);
    float4 pn0 = spos[nb0];
    float d0x = pn0.x - pi.x, d0y = pn0.y - pi.y, d0z = pn0.z - pi.z;
    float n0  = sqrtf(d0x*d0x + d0y*d0y + d0z*d0z);
    float inv0 = 1.f / fmaxf(n0, 1e-12f);
    d0x *= inv0; d0y *= inv0; d0z *= inv0;

    float cosv = 1.f;
    if (lane > 0) {
        float4 pn = spos[nb];
        float dx = pn.x - pi.x, dy = pn.y - pi.y, dz = pn.z - pi.z;
        float nrm = sqrtf(dx*dx + dy*dy + dz*dz);
        float inv = 1.f / fmaxf(nrm, 1e-12f);
        cosv = (dx*d0x + dy*d0y + dz*d0z) * inv;
    }
    const float gb   = fmaxf(dist * Spos, 0.f) * mk;
    const float gate = 1.f / (1.f + __expf(-gb));

    float G = gate;
    #pragma unroll
    for (int o = 16; o; o >>= 1) G += __shfl_xor_sync(FULLM, G, o);

    const size_t base = ((size_t)slice * NN + i) * KK;
    g_nbr  [base + lane] = nb;
    g_theta[base + lane] = cosv * mk;
    g_gate [base + lane] = gate;
    if (lane == 0) g_gsum[(size_t)slice*NN + i] = G;
}

// ---------------------------------------------------------------------------
// Kernel 2 v4: 32 nodes/block (grid 256), gather + dual GEMV (4m x 2n tile).
// smem ~98KB -> 2 blocks/SM.
// ---------------------------------------------------------------------------
#define O_SSW  0          // [f][64]  8192
#define O_SAWT 8192       // [f][64]  8192
#define O_SU   16384      // [f][p34] 4352
#define O_STH  20736      // [f][p34] 4352
#define O_ARAW 16384      // overlay [64][129] = 8256 (dead before su/sth)
#define SM2F   25088      // floats -> 100352 bytes

__global__ __launch_bounds__(256) void fuse_kernel(
    const float* __restrict__ node_fea, const float* __restrict__ node_mask,
    const float* __restrict__ aw, const float* __restrict__ sw,
    float* __restrict__ out)
{
    extern __shared__ float sm2[];
    float* ssw  = sm2 + O_SSW;
    float* sawT = sm2 + O_SAWT;
    float* su   = sm2 + O_SU;
    float* sth  = sm2 + O_STH;
    float* araw = sm2 + O_ARAW;

    const int tid = threadIdx.x;
    const int b   = blockIdx.x >> 6;          // 64 blocks per batch
    const int n0  = (blockIdx.x & 63) * 32;

    // stage weights: sw [f][64] direct; aw [64 m][128 f] transposed via pad
    for (int idx = tid; idx < MM*128; idx += 256) {
        int m = idx >> 7, f = idx & 127;
        araw[m*129 + f] = aw[idx];
        ssw[idx] = sw[idx];
    }
    __syncthreads();
    for (int idx = tid; idx < MM*128; idx += 256) {
        int f = idx >> 6, m = idx & 63;
        sawT[idx] = araw[m*129 + f];
    }
    __syncthreads();                           // araw dead; su/sth safe now

    // stage theta -> [f = k*4+c][n], pitch 34
    for (int idx = tid; idx < 4096; idx += 256) {
        int c = idx >> 10, r = idx & 1023, n = r >> 5, k = r & 31;
        sth[(k*4 + c)*34 + n] =
            g_theta[(((size_t)(b*CC + c))*NN + n0 + n)*KK + k];
    }

    // phase A: thread = (c, nn, half) builds 8 nbr-f + 8 self-f of su[f][n]
    {
        const int c = tid >> 6, r = tid & 63, nn = r >> 1, half = r & 1;
        const float* nf = node_fea + (size_t)(b*CC + c) * NN * DD;
        const float mk = node_mask[b*NN + n0 + nn];
        const float G  = g_gsum[(size_t)(b*CC + c)*NN + n0 + nn];
        const size_t eb = ((size_t)(b*CC + c)*NN + n0 + nn) * KK;

        float4 a0 = {0,0,0,0}, a1 = {0,0,0,0};
        #pragma unroll 2
        for (int k4 = 0; k4 < 8; k4++) {
            float4 g4 = __ldg((const float4*)(g_gate + eb) + k4);
            int4   n4 = __ldg((const int4*)  (g_nbr  + eb) + k4);
            const float gs[4] = {g4.x, g4.y, g4.z, g4.w};
            const int   ns[4] = {n4.x, n4.y, n4.z, n4.w};
            #pragma unroll
            for (int e = 0; e < 4; e++) {
                const float4* vp =
                    (const float4*)(nf + (size_t)ns[e]*DD) + half*2;
                float4 v0 = __ldg(vp), v1 = __ldg(vp + 1);
                float g = gs[e];
                a0.x = fmaf(g, v0.x, a0.x); a0.y = fmaf(g, v0.y, a0.y);
                a0.z = fmaf(g, v0.z, a0.z); a0.w = fmaf(g, v0.w, a0.w);
                a1.x = fmaf(g, v1.x, a1.x); a1.y = fmaf(g, v1.y, a1.y);
                a1.z = fmaf(g, v1.z, a1.z); a1.w = fmaf(g, v1.w, a1.w);
            }
        }
        const int fn = c*32 + 16 + half*8;     // neighbor block (masked)
        su[(fn+0)*34+nn] = a0.x*mk;  su[(fn+1)*34+nn] = a0.y*mk;
        su[(fn+2)*34+nn] = a0.z*mk;  su[(fn+3)*34+nn] = a0.w*mk;
        su[(fn+4)*34+nn] = a1.x*mk;  su[(fn+5)*34+nn] = a1.y*mk;
        su[(fn+6)*34+nn] = a1.z*mk;  su[(fn+7)*34+nn] = a1.w*mk;

        const float Gm = G * mk;               // self block
        const float4* fp = (const float4*)(nf + (size_t)(n0+nn)*DD) + half*2;
        float4 f0 = __ldg(fp), f1 = __ldg(fp + 1);
        const int fs = c*32 + half*8;
        su[(fs+0)*34+nn] = Gm*f0.x;  su[(fs+1)*34+nn] = Gm*f0.y;
        su[(fs+2)*34+nn] = Gm*f0.z;  su[(fs+3)*34+nn] = Gm*f0.w;
        su[(fs+4)*34+nn] = Gm*f1.x;  su[(fs+5)*34+nn] = Gm*f1.y;
        su[(fs+6)*34+nn] = Gm*f1.z;  su[(fs+7)*34+nn] = Gm*f1.w;
    }
    __syncthreads();

    // phase B: thread tile 4m x 2n
    {
        const int mg = (tid & 15) * 4;
        const int ng = tid >> 4;               // n = ng*2 + {0,1}
        float acc[4][2];
        #pragma unroll
        for (int a = 0; a < 4; a++) { acc[a][0] = 0.f; acc[a][1] = 0.f; }

        #pragma unroll 4
        for (int f = 0; f < 128; f++) {
            float4 w1 = *(const float4*)&ssw [f*64 + mg];
            float4 w2 = *(const float4*)&sawT[f*64 + mg];
            float2 uu = *(const float2*)&su  [f*34 + ng*2];
            float2 tt = *(const float2*)&sth [f*34 + ng*2];
            const float wm1[4] = {w1.x, w1.y, w1.z, w1.w};
            const float wm2[4] = {w2.x, w2.y, w2.z, w2.w};
            #pragma unroll
            for (int a = 0; a < 4; a++) {
                acc[a][0] = fmaf(wm1[a], uu.x, fmaf(wm2[a], tt.x, acc[a][0]));
                acc[a][1] = fmaf(wm1[a], uu.y, fmaf(wm2[a], tt.y, acc[a][1]));
            }
        }

        const float mk0 = node_mask[b*NN + n0 + ng*2];
        const float mk1 = node_mask[b*NN + n0 + ng*2 + 1];
        #pragma unroll
        for (int a = 0; a < 4; a++) {
            float v0 = acc[a][0], v1 = acc[a][1];
            v0 = (v0 >= 0.f) ? v0 : 0.01f*v0;
            v1 = (v1 >= 0.f) ? v1 : 0.01f*v1;
            float2 o2 = make_float2(v0*mk0, v1*mk1);
            *(float2*)&out[((size_t)b*MM + mg + a)*NN + n0 + ng*2] = o2;
        }
    }
}

// ---------------------------------------------------------------------------
extern "C" void kernel_launch(void* const* d_in, const int* in_sizes, int n_in,
                              void* d_out, int out_size)
{
    const float* pos       = (const float*)d_in[0];
    const float* node_fea  = (const float*)d_in[1];
    const float* node_mask = (const float*)d_in[2];
    const float* aw        = (const float*)d_in[3];
    const float* sw        = (const float*)d_in[4];
    const float* rw1       = (const float*)d_in[5];
    const float* rw2       = (const float*)d_in[6];
    float* out = (float*)d_out;

    cudaFuncSetAttribute(fuse_kernel,
        cudaFuncAttributeMaxDynamicSharedMemorySize, SM2F*4);

    knn_kernel<<<dim3(NN/ROWS1, BSZ*CC), 512>>>(pos, node_mask, rw1, rw2);
    fuse_kernel<<<BSZ*(NN/32), 256, SM2F*4>>>(node_fea, node_mask, aw, sw, out);
}

// round 5
// speedup vs baseline: 1.0899x; 1.0899x over previous
#include <cuda_runtime.h>
#include <math.h>

#define BSZ 4
#define CC  4
#define NN  2048
#define DD  16
#define KK  32
#define MM  64
#define FULLM 0xffffffffu
typedef unsigned long long ull;
#define INF32 0xffffffffu
#define INF64 0xFFFFFFFFFFFFFFFFull

// scratch (allocation-free rule: device globals)
__device__ int   g_nbr  [BSZ*CC*NN*KK];
__device__ float g_theta[BSZ*CC*NN*KK];
__device__ float g_gate [BSZ*CC*NN*KK];
__device__ float g_gsum [BSZ*CC*NN];
__device__ float g_awT  [128*MM];

__device__ __forceinline__ ull warpmin64(ull p) {
    #pragma unroll
    for (int o = 16; o; o >>= 1) {
        ull q = __shfl_xor_sync(FULLM, p, o);
        if (q < p) p = q;
    }
    return p;
}

// sorted top-3 insert on u32 (d, j) pairs; strict < keeps earlier j on ties
#define INS3(dv, jv, h0d, h0j, h1d, h1j, h2d, h2j) do {                    \
    bool c2 = (dv) < (h2d); bool c1 = (dv) < (h1d); bool c0 = (dv) < (h0d);\
    (h2d) = c1 ? (h1d) : (c2 ? (dv) : (h2d));                              \
    (h2j) = c1 ? (h1j) : (c2 ? (jv) : (h2j));                              \
    (h1d) = c0 ? (h0d) : (c1 ? (dv) : (h1d));                              \
    (h1j) = c0 ? (h0j) : (c1 ? (jv) : (h1j));                              \
    (h0d) = c0 ? (dv) : (h0d);                                             \
    (h0j) = c0 ? (jv) : (h0j);                                             \
} while (0)

// ---------------------------------------------------------------------------
// transpose angle_weight [64 m][128 f] -> g_awT [128 f][64 m] (tiny, once)
// ---------------------------------------------------------------------------
__global__ void transpose_aw_kernel(const float* __restrict__ aw) {
    int idx = blockIdx.x * 256 + threadIdx.x;     // 8192
    int f = idx >> 6, m = idx & 63;
    g_awT[idx] = aw[m*128 + f];
}

// ---------------------------------------------------------------------------
// Kernel 1 v5: 2 rows per warp, u32 keys, REDUX extraction, rare refill.
// Block 512 = 16 warps = 32 rows. Grid (64, 16). 32KB smem, 3 blocks/SM.
// ---------------------------------------------------------------------------
__device__ __forceinline__ void refill_seg(
    int w, unsigned dL, unsigned jL, float4 pi, int lane,
    unsigned& h0d, unsigned& h0j, unsigned& h1d, unsigned& h1j,
    unsigned& h2d, unsigned& h2j, const float4* spos)
{
    const ull L = ((ull)dL << 32) | jL;           // largest extracted so far
    const int j1 = lane*32 + w, j2 = j1 + 1024;
    float4 a  = spos[j1];
    float4 bb = spos[j2];
    float dota = fmaf(pi.z, a.z,  fmaf(pi.y, a.y,  pi.x * a.x));
    float dotb = fmaf(pi.z, bb.z, fmaf(pi.y, bb.y, pi.x * bb.x));
    float da = fmaxf(fmaf(-2.f, dota, a.w)  + pi.w, 0.f);
    float db = fmaxf(fmaf(-2.f, dotb, bb.w) + pi.w, 0.f);
    ull k1 = ((ull)__float_as_uint(da) << 32) | (unsigned)j1;
    ull k2 = ((ull)__float_as_uint(db) << 32) | (unsigned)j2;
    if (k1 <= L) k1 = INF64;
    if (k2 <= L) k2 = INF64;
    #pragma unroll
    for (int r = 0; r < 3; r++) {
        ull m  = (k1 < k2) ? k1 : k2;
        ull wm = warpmin64(m);
        if (lane == w) {
            unsigned wd = (unsigned)(wm >> 32), wj = (unsigned)wm;
            if (r == 0)      { h0d = wd; h0j = wj; }
            else if (r == 1) { h1d = wd; h1j = wj; }
            else             { h2d = wd; h2j = wj; }
        }
        if (k1 == wm) k1 = INF64; else if (k2 == wm) k2 = INF64;
    }
}

__device__ __forceinline__ void emit_row(
    int slice, int b, int i, float4 pi, unsigned nbd, int nbj,
    float Spos, const float* node_mask, const float4* spos, int lane)
{
    const float mk   = node_mask[b*NN + i];
    const float dist = __uint_as_float(nbd);
    const int   nb   = nbj;

    const int nb0 = __shfl_sync(FULLM, nbj, 0);
    float4 pn0 = spos[nb0];
    float d0x = pn0.x - pi.x, d0y = pn0.y - pi.y, d0z = pn0.z - pi.z;
    float n0  = sqrtf(d0x*d0x + d0y*d0y + d0z*d0z);
    float inv0 = 1.f / fmaxf(n0, 1e-12f);
    d0x *= inv0; d0y *= inv0; d0z *= inv0;

    float cosv = 1.f;
    if (lane > 0) {
        float4 pn = spos[nb];
        float dx = pn.x - pi.x, dy = pn.y - pi.y, dz = pn.z - pi.z;
        float nrm = sqrtf(dx*dx + dy*dy + dz*dz);
        float inv = 1.f / fmaxf(nrm, 1e-12f);
        cosv = (dx*d0x + dy*d0y + dz*d0z) * inv;
    }
    const float gb   = fmaxf(dist * Spos, 0.f) * mk;
    const float gate = 1.f / (1.f + __expf(-gb));

    float G = gate;
    #pragma unroll
    for (int o = 16; o; o >>= 1) G += __shfl_xor_sync(FULLM, G, o);

    const size_t base = ((size_t)slice * NN + i) * KK;
    g_nbr  [base + lane] = nb;
    g_theta[base + lane] = cosv * mk;
    g_gate [base + lane] = gate;
    if (lane == 0) g_gsum[(size_t)slice*NN + i] = G;
}

__global__ __launch_bounds__(512, 3) void knn_kernel(
    const float* __restrict__ pos, const float* __restrict__ node_mask,
    const float* __restrict__ rw1, const float* __restrict__ rw2)
{
    __shared__ float4 spos[NN];            // 32KB
    __shared__ float sSpos;

    const int tid  = threadIdx.x;
    const int warp = tid >> 5;
    const int lane = tid & 31;
    const int slice = blockIdx.y;          // b*C + c
    const int b     = slice >> 2;
    const float* p  = pos + (size_t)slice * NN * 3;

    for (int j = tid; j < NN; j += 512) {
        float x = p[3*j], y = p[3*j+1], z = p[3*j+2];
        float q = fmaf(z, z, fmaf(y, y, x*x));
        spos[j] = make_float4(x, y, z, q);
    }

    // gate MLP collapses: relu(sum_m relu(d*w1)*w2) = relu(d*Spos) for d>=0
    if (tid < 32) {
        float a1 = rw1[tid],    w1v = rw2[tid];
        float a2 = rw1[tid+32], w2v = rw2[tid+32];
        float sp = fmaf(fmaxf(a1, 0.f), w1v, fmaxf(a2, 0.f) * w2v);
        #pragma unroll
        for (int o = 16; o; o >>= 1) sp += __shfl_xor_sync(FULLM, sp, o);
        if (tid == 0) sSpos = sp;
    }
    __syncthreads();

    const int iA = blockIdx.x * 32 + warp * 2;
    const int iB = iA + 1;
    const float4 piA = spos[iA];
    const float4 piB = spos[iB];

    // distance pass: lane owns segment {j : j%32 == lane}; sorted top-3 each row
    unsigned a0d = INF32, a1d = INF32, a2d = INF32, a0j = 0, a1j = 0, a2j = 0;
    unsigned b0d = INF32, b1d = INF32, b2d = INF32, b0j = 0, b1j = 0, b2j = 0;
    #pragma unroll 4
    for (int t = 0; t < 64; t++) {
        const unsigned j = (unsigned)(t*32 + lane);
        float4 pj = spos[j];
        float dotA = fmaf(piA.z, pj.z, fmaf(piA.y, pj.y, piA.x * pj.x));
        float dA   = fmaxf(fmaf(-2.f, dotA, pj.w) + piA.w, 0.f);
        unsigned uA = __float_as_uint(dA);
        INS3(uA, j, a0d, a0j, a1d, a1j, a2d, a2j);
        float dotB = fmaf(piB.z, pj.z, fmaf(piB.y, pj.y, piB.x * pj.x));
        float dB   = fmaxf(fmaf(-2.f, dotB, pj.w) + piB.w, 0.f);
        unsigned uB = __float_as_uint(dB);
        INS3(uB, j, b0d, b0j, b1d, b1j, b2d, b2j);
    }

    // extract 33 smallest ascending (d, j) for both rows; lane e-1 keeps e-th
    unsigned nbdA = 0, nbdB = 0; int nbjA = 0, nbjB = 0;
    #pragma unroll 1
    for (int e = 0; e <= 32; e++) {
        unsigned dminA = __reduce_min_sync(FULLM, a0d);
        unsigned cjA   = (a0d == dminA) ? a0j : INF32;
        unsigned jminA = __reduce_min_sync(FULLM, cjA);
        unsigned dminB = __reduce_min_sync(FULLM, b0d);
        unsigned cjB   = (b0d == dminB) ? b0j : INF32;
        unsigned jminB = __reduce_min_sync(FULLM, cjB);
        if (lane == e - 1) {
            nbdA = dminA; nbjA = (int)jminA;
            nbdB = dminB; nbjB = (int)jminB;
        }
        if (e == 32) break;
        const int wA = (int)(jminA & 31u);
        const int wB = (int)(jminB & 31u);
        if (lane == wA) { a0d = a1d; a0j = a1j; a1d = a2d; a1j = a2j; a2d = INF32; }
        if (lane == wB) { b0d = b1d; b0j = b1j; b1d = b2d; b1j = b2j; b2d = INF32; }
        unsigned hwA = __shfl_sync(FULLM, a0d, wA);
        unsigned hwB = __shfl_sync(FULLM, b0d, wB);
        if (hwA == INF32)
            refill_seg(wA, dminA, jminA, piA, lane, a0d, a0j, a1d, a1j, a2d, a2j, spos);
        if (hwB == INF32)
            refill_seg(wB, dminB, jminB, piB, lane, b0d, b0j, b1d, b1j, b2d, b2j, spos);
    }

    const float Spos = sSpos;
    emit_row(slice, b, iA, piA, nbdA, nbjA, Spos, node_mask, spos, lane);
    emit_row(slice, b, iB, piB, nbdB, nbjB, Spos, node_mask, spos, lane);
}

// ---------------------------------------------------------------------------
// Kernel 2 v5: 32 nodes/block, weights from global (L1), 35KB smem,
// 5 blocks/SM. Block 256, grid 256.
// ---------------------------------------------------------------------------
__global__ __launch_bounds__(256, 5) void fuse_kernel(
    const float* __restrict__ node_fea, const float* __restrict__ node_mask,
    const float* __restrict__ sw, float* __restrict__ out)
{
    __shared__ float su [128*34];          // [f][n pitch34]
    __shared__ float sth[128*34];

    const int tid = threadIdx.x;
    const int b   = blockIdx.x >> 6;       // 64 blocks per batch
    const int n0  = (blockIdx.x & 63) * 32;

    // stage theta -> [f = k*4+c][n]
    for (int idx = tid; idx < 4096; idx += 256) {
        int c = idx >> 10, r = idx & 1023, n = r >> 5, k = r & 31;
        sth[(k*4 + c)*34 + n] =
            g_theta[(((size_t)(b*CC + c))*NN + n0 + n)*KK + k];
    }

    // phase A: thread = (c, nn, half) builds 8 nbr-f + 8 self-f of su[f][n]
    {
        const int c = tid >> 6, r = tid & 63, nn = r >> 1, half = r & 1;
        const float* nf = node_fea + (size_t)(b*CC + c) * NN * DD;
        const float mk = node_mask[b*NN + n0 + nn];
        const float G  = g_gsum[(size_t)(b*CC + c)*NN + n0 + nn];
        const size_t eb = ((size_t)(b*CC + c)*NN + n0 + nn) * KK;

        float4 a0 = {0,0,0,0}, a1 = {0,0,0,0};
        #pragma unroll 2
        for (int k4 = 0; k4 < 8; k4++) {
            float4 g4 = __ldg((const float4*)(g_gate + eb) + k4);
            int4   n4 = __ldg((const int4*)  (g_nbr  + eb) + k4);
            const float gs[4] = {g4.x, g4.y, g4.z, g4.w};
            const int   ns[4] = {n4.x, n4.y, n4.z, n4.w};
            #pragma unroll
            for (int e = 0; e < 4; e++) {
                const float4* vp =
                    (const float4*)(nf + (size_t)ns[e]*DD) + half*2;
                float4 v0 = __ldg(vp), v1 = __ldg(vp + 1);
                float g = gs[e];
                a0.x = fmaf(g, v0.x, a0.x); a0.y = fmaf(g, v0.y, a0.y);
                a0.z = fmaf(g, v0.z, a0.z); a0.w = fmaf(g, v0.w, a0.w);
                a1.x = fmaf(g, v1.x, a1.x); a1.y = fmaf(g, v1.y, a1.y);
                a1.z = fmaf(g, v1.z, a1.z); a1.w = fmaf(g, v1.w, a1.w);
            }
        }
        const int fn = c*32 + 16 + half*8;     // neighbor block (masked)
        su[(fn+0)*34+nn] = a0.x*mk;  su[(fn+1)*34+nn] = a0.y*mk;
        su[(fn+2)*34+nn] = a0.z*mk;  su[(fn+3)*34+nn] = a0.w*mk;
        su[(fn+4)*34+nn] = a1.x*mk;  su[(fn+5)*34+nn] = a1.y*mk;
        su[(fn+6)*34+nn] = a1.z*mk;  su[(fn+7)*34+nn] = a1.w*mk;

        const float Gm = G * mk;               // self block
        const float4* fp = (const float4*)(nf + (size_t)(n0+nn)*DD) + half*2;
        float4 f0 = __ldg(fp), f1 = __ldg(fp + 1);
        const int fs = c*32 + half*8;
        su[(fs+0)*34+nn] = Gm*f0.x;  su[(fs+1)*34+nn] = Gm*f0.y;
        su[(fs+2)*34+nn] = Gm*f0.z;  su[(fs+3)*34+nn] = Gm*f0.w;
        su[(fs+4)*34+nn] = Gm*f1.x;  su[(fs+5)*34+nn] = Gm*f1.y;
        su[(fs+6)*34+nn] = Gm*f1.z;  su[(fs+7)*34+nn] = Gm*f1.w;
    }
    __syncthreads();

    // phase B: thread tile 4m x 2n, weights streamed from global (L1-hot)
    {
        const int mg = (tid & 15) * 4;
        const int ng = tid >> 4;               // n = ng*2 + {0,1}
        float acc[4][2];
        #pragma unroll
        for (int a = 0; a < 4; a++) { acc[a][0] = 0.f; acc[a][1] = 0.f; }

        #pragma unroll 4
        for (int f = 0; f < 128; f++) {
            float4 w1 = __ldg((const float4*)(sw    + f*64 + mg));
            float4 w2 = __ldg((const float4*)(g_awT + f*64 + mg));
            float2 uu = *(const float2*)&su [f*34 + ng*2];
            float2 tt = *(const float2*)&sth[f*34 + ng*2];
            const float wm1[4] = {w1.x, w1.y, w1.z, w1.w};
            const float wm2[4] = {w2.x, w2.y, w2.z, w2.w};
            #pragma unroll
            for (int a = 0; a < 4; a++) {
                acc[a][0] = fmaf(wm1[a], uu.x, fmaf(wm2[a], tt.x, acc[a][0]));
                acc[a][1] = fmaf(wm1[a], uu.y, fmaf(wm2[a], tt.y, acc[a][1]));
            }
        }

        const float mk0 = node_mask[b*NN + n0 + ng*2];
        const float mk1 = node_mask[b*NN + n0 + ng*2 + 1];
        #pragma unroll
        for (int a = 0; a < 4; a++) {
            float v0 = acc[a][0], v1 = acc[a][1];
            v0 = (v0 >= 0.f) ? v0 : 0.01f*v0;
            v1 = (v1 >= 0.f) ? v1 : 0.01f*v1;
            float2 o2 = make_float2(v0*mk0, v1*mk1);
            *(float2*)&out[((size_t)b*MM + mg + a)*NN + n0 + ng*2] = o2;
        }
    }
}

// ---------------------------------------------------------------------------
extern "C" void kernel_launch(void* const* d_in, const int* in_sizes, int n_in,
                              void* d_out, int out_size)
{
    const float* pos       = (const float*)d_in[0];
    const float* node_fea  = (const float*)d_in[1];
    const float* node_mask = (const float*)d_in[2];
    const float* aw        = (const float*)d_in[3];
    const float* sw        = (const float*)d_in[4];
    const float* rw1       = (const float*)d_in[5];
    const float* rw2       = (const float*)d_in[6];
    float* out = (float*)d_out;

    transpose_aw_kernel<<<32, 256>>>(aw);
    knn_kernel<<<dim3(NN/32, BSZ*CC), 512>>>(pos, node_mask, rw1, rw2);
    fuse_kernel<<<BSZ*(NN/32), 256>>>(node_fea, node_mask, sw, out);
}